// round 1
// baseline (speedup 1.0000x reference)
#include <cuda_runtime.h>
#include <cstdint>
#include <cstddef>

// Problem constants (fixed shapes for this problem)
#define E_NUM 8
#define T_MAX 4096
#define DIN   2048
#define DOUT  2048

#define BM 128
#define BN 128
#define BK 32

// ---------------- scratch (device globals; no allocations allowed) ----------
__device__ int   g_cnt[E_NUM];
__device__ int   g_tok[E_NUM * T_MAX];
__device__ float g_gate[E_NUM * T_MAX];

// ---------------- helpers ----------------------------------------------------
__device__ __forceinline__ unsigned f2tf32(float f) {
    unsigned u;
    asm("cvt.rna.tf32.f32 %0, %1;" : "=r"(u) : "f"(f));
    return u;
}

// ---------------- kernel 1: zero output + counters ---------------------------
__global__ void zero_init_kernel(float4* __restrict__ out, int n4) {
    if (blockIdx.x == 0 && threadIdx.x < E_NUM) g_cnt[threadIdx.x] = 0;
    float4 z = make_float4(0.f, 0.f, 0.f, 0.f);
    for (int i = blockIdx.x * blockDim.x + threadIdx.x; i < n4;
         i += gridDim.x * blockDim.x)
        out[i] = z;
}

// ---------------- kernel 2: router (softmax + top-2 + gather lists) ----------
__global__ void router_kernel(const float* __restrict__ logits, int T) {
    int t = blockIdx.x * blockDim.x + threadIdx.x;
    if (t >= T) return;
    float l[E_NUM];
#pragma unroll
    for (int e = 0; e < E_NUM; e++) l[e] = logits[t * E_NUM + e];

    int i1 = 0; float v1 = l[0];
#pragma unroll
    for (int e = 1; e < E_NUM; e++)
        if (l[e] > v1) { v1 = l[e]; i1 = e; }
    int i2 = -1; float v2 = -3.4e38f;
#pragma unroll
    for (int e = 0; e < E_NUM; e++)
        if (e != i1 && l[e] > v2) { v2 = l[e]; i2 = e; }

    // renormalized top-2 softmax weights: w1 = p1/(p1+p2) = 1/(1+exp(l2-l1))
    float w1 = 1.0f / (1.0f + expf(v2 - v1));
    float w2 = 1.0f - w1;

    int p1 = atomicAdd(&g_cnt[i1], 1);
    g_tok[i1 * T_MAX + p1]  = t;
    g_gate[i1 * T_MAX + p1] = w1;
    int p2 = atomicAdd(&g_cnt[i2], 1);
    g_tok[i2 * T_MAX + p2]  = t;
    g_gate[i2 * T_MAX + p2] = w2;
}

// ---------------- kernel 3: grouped TF32 GEMM --------------------------------
// C[token, n] += gate * ( X[token,:] . W[e,n,:] + b[e,n] )
// A (X rows, gathered) and B (W_e rows) are both K-major -> TN GEMM.
//
// SMEM layout per k8-slice: s[slice][row][8] where within the 8 floats the
// k order is pair-interleaved: (k, k+4) at float2-index c, then XOR-swizzled
// by ((row>>2)&3) so both STS and fragment LDS.64 are conflict-free.
__device__ __forceinline__ void sts_group(float* base, int row,
                                          const float4& v0, const float4& v1) {
    int sw = (row >> 2) & 3;
    float2* p = (float2*)base;
    float2 t;
    t.x = __uint_as_float(f2tf32(v0.x)); t.y = __uint_as_float(f2tf32(v1.x));
    p[0 ^ sw] = t;
    t.x = __uint_as_float(f2tf32(v0.y)); t.y = __uint_as_float(f2tf32(v1.y));
    p[1 ^ sw] = t;
    t.x = __uint_as_float(f2tf32(v0.z)); t.y = __uint_as_float(f2tf32(v1.z));
    p[2 ^ sw] = t;
    t.x = __uint_as_float(f2tf32(v0.w)); t.y = __uint_as_float(f2tf32(v1.w));
    p[3 ^ sw] = t;
}

__global__ void __launch_bounds__(256, 1)
moe_gemm_kernel(const float* __restrict__ X, const float* __restrict__ Wt,
                const float* __restrict__ Bias, float* __restrict__ Out) {
    int e   = blockIdx.z;
    int cnt = g_cnt[e];
    int m0  = blockIdx.y * BM;
    if (m0 >= cnt) return;                 // empty tile: exit fast
    int n0  = blockIdx.x * BN;

    __shared__ float sA[4][BM][8];
    __shared__ float sB[4][BN][8];
    __shared__ int   s_tok[BM];
    __shared__ float s_gate[BM];
    __shared__ float s_bias[BN];

    int tid = threadIdx.x;

    if (tid < BM) {
        int r = m0 + tid;
        if (r < cnt) {
            s_tok[tid]  = g_tok[e * T_MAX + r];
            s_gate[tid] = g_gate[e * T_MAX + r];
        } else {
            s_tok[tid]  = -1;
            s_gate[tid] = 0.0f;
        }
    }
    if (tid < BN) s_bias[tid] = Bias[e * DOUT + n0 + tid];
    __syncthreads();

    // ---- staging roles: thread handles row (tid&127), k8-groups g and g+2 ----
    int rrow = tid & 127;
    int rgrp = tid >> 7;                               // 0 or 1
    int tokA = s_tok[rrow];
    const float* aptr = (tokA >= 0)
        ? (X + (size_t)tokA * DIN + rgrp * 8) : (const float*)0;
    const float* bptr = Wt + ((size_t)e * DOUT + (size_t)(n0 + rrow)) * DIN + rgrp * 8;

    int lane = tid & 31;
    int warp = tid >> 5;
    int wm = warp & 3;      // 4 warps along M
    int wn = warp >> 2;     // 2 warps along N
    int g  = lane >> 2;     // group id 0..7
    int c  = lane & 3;      // thread-in-group 0..3

    float acc[2][8][4];
#pragma unroll
    for (int i = 0; i < 2; i++)
#pragma unroll
        for (int j = 0; j < 8; j++)
#pragma unroll
            for (int k = 0; k < 4; k++) acc[i][j][k] = 0.0f;

    float4 ra0, ra1, ra2, ra3, rb0, rb1, rb2, rb3;

#define LDG_STEP(k0)                                                          \
    do {                                                                      \
        if (aptr) {                                                           \
            ra0 = *(const float4*)(aptr + (k0));                              \
            ra1 = *(const float4*)(aptr + (k0) + 4);                          \
            ra2 = *(const float4*)(aptr + (k0) + 16);                         \
            ra3 = *(const float4*)(aptr + (k0) + 20);                         \
        } else {                                                              \
            ra0 = ra1 = ra2 = ra3 = make_float4(0.f, 0.f, 0.f, 0.f);          \
        }                                                                     \
        rb0 = *(const float4*)(bptr + (k0));                                  \
        rb1 = *(const float4*)(bptr + (k0) + 4);                              \
        rb2 = *(const float4*)(bptr + (k0) + 16);                             \
        rb3 = *(const float4*)(bptr + (k0) + 20);                             \
    } while (0)

#define STS_STEP()                                                            \
    do {                                                                      \
        sts_group(&sA[rgrp][rrow][0],     rrow, ra0, ra1);                    \
        sts_group(&sA[rgrp + 2][rrow][0], rrow, ra2, ra3);                    \
        sts_group(&sB[rgrp][rrow][0],     rrow, rb0, rb1);                    \
        sts_group(&sB[rgrp + 2][rrow][0], rrow, rb2, rb3);                    \
    } while (0)

#define COMPUTE_STEP()                                                        \
    do {                                                                      \
        _Pragma("unroll")                                                     \
        for (int s = 0; s < 4; s++) {                                         \
            unsigned afr[2][4];                                               \
            _Pragma("unroll")                                                 \
            for (int mt = 0; mt < 2; mt++) {                                  \
                int row  = wm * 32 + mt * 16 + g;                             \
                int sw0  = (row >> 2) & 3;                                    \
                float2 lo = *(float2*)&sA[s][row][(c ^ sw0) * 2];             \
                int rowh = row + 8;                                           \
                int sw1  = (rowh >> 2) & 3;                                   \
                float2 hi = *(float2*)&sA[s][rowh][(c ^ sw1) * 2];            \
                afr[mt][0] = __float_as_uint(lo.x);                           \
                afr[mt][1] = __float_as_uint(hi.x);                           \
                afr[mt][2] = __float_as_uint(lo.y);                           \
                afr[mt][3] = __float_as_uint(hi.y);                           \
            }                                                                 \
            _Pragma("unroll")                                                 \
            for (int nt = 0; nt < 8; nt++) {                                  \
                int n   = wn * 64 + nt * 8 + g;                               \
                int swb = (n >> 2) & 3;                                       \
                float2 bb = *(float2*)&sB[s][n][(c ^ swb) * 2];               \
                unsigned bf0 = __float_as_uint(bb.x);                         \
                unsigned bf1 = __float_as_uint(bb.y);                         \
                _Pragma("unroll")                                             \
                for (int mt = 0; mt < 2; mt++) {                              \
                    asm volatile(                                             \
                        "mma.sync.aligned.m16n8k8.row.col.f32.tf32.tf32.f32 " \
                        "{%0,%1,%2,%3}, {%4,%5,%6,%7}, {%8,%9}, "             \
                        "{%0,%1,%2,%3};\n"                                    \
                        : "+f"(acc[mt][nt][0]), "+f"(acc[mt][nt][1]),         \
                          "+f"(acc[mt][nt][2]), "+f"(acc[mt][nt][3])          \
                        : "r"(afr[mt][0]), "r"(afr[mt][1]),                   \
                          "r"(afr[mt][2]), "r"(afr[mt][3]),                   \
                          "r"(bf0), "r"(bf1));                                \
                }                                                             \
            }                                                                 \
        }                                                                     \
    } while (0)

    // prologue
    LDG_STEP(0);
    STS_STEP();
    __syncthreads();

    for (int k0 = BK; k0 <= DIN - BK; k0 += BK) {
        LDG_STEP(k0);        // prefetch next tile into registers
        COMPUTE_STEP();      // compute current tile from SMEM
        __syncthreads();
        STS_STEP();
        __syncthreads();
    }
    COMPUTE_STEP();          // last tile

    // ---- epilogue: gate * (acc + bias), scatter-add (exactly 2 adds/elem) ----
#pragma unroll
    for (int mt = 0; mt < 2; mt++) {
        int rbase = wm * 32 + mt * 16 + g;
        int t0 = s_tok[rbase];
        int t1 = s_tok[rbase + 8];
        float g0 = s_gate[rbase];
        float g1 = s_gate[rbase + 8];
#pragma unroll
        for (int nt = 0; nt < 8; nt++) {
            int ncol = wn * 64 + nt * 8 + c * 2;   // local col in [0,BN)
            int col  = n0 + ncol;
            float b0v = s_bias[ncol];
            float b1v = s_bias[ncol + 1];
            if (t0 >= 0) {
                atomicAdd(&Out[(size_t)t0 * DOUT + col],     g0 * (acc[mt][nt][0] + b0v));
                atomicAdd(&Out[(size_t)t0 * DOUT + col + 1], g0 * (acc[mt][nt][1] + b1v));
            }
            if (t1 >= 0) {
                atomicAdd(&Out[(size_t)t1 * DOUT + col],     g1 * (acc[mt][nt][2] + b0v));
                atomicAdd(&Out[(size_t)t1 * DOUT + col + 1], g1 * (acc[mt][nt][3] + b1v));
            }
        }
    }
#undef LDG_STEP
#undef STS_STEP
#undef COMPUTE_STEP
}

// ---------------- launcher ---------------------------------------------------
extern "C" void kernel_launch(void* const* d_in, const int* in_sizes, int n_in,
                              void* d_out, int out_size) {
    const float* X      = (const float*)d_in[0];   // hidden_states [B,S,DIN]
    const float* logits = (const float*)d_in[1];   // router_logits [T,E]
    const float* W      = (const float*)d_in[2];   // W [E,DOUT,DIN]
    const float* B      = (const float*)d_in[3];   // b [E,DOUT]
    float* Out          = (float*)d_out;           // [T, DOUT]

    int T  = in_sizes[1] / E_NUM;                  // 4096
    int n4 = out_size / 4;

    zero_init_kernel<<<2048, 256>>>((float4*)Out, n4);
    router_kernel<<<(T + 255) / 256, 256>>>(logits, T);

    dim3 grid(DOUT / BN, (T + BM - 1) / BM, E_NUM);
    moe_gemm_kernel<<<grid, 256>>>(X, W, B, Out);
}

// round 3
// speedup vs baseline: 1.2343x; 1.2343x over previous
#include <cuda_runtime.h>
#include <cstdint>
#include <cstddef>

// ---------------- problem constants ----------------
#define E_NUM 8
#define T_MAX 4096
#define DIN   2048
#define DOUT  2048

// GEMM tiling: CTA 128x256, 8 warps (2 M x 4 N), warp tile 64x64, BK=32
#define BM 128
#define BN 256
#define BK 32
#define STAGES 3
#define KITERS (DIN / BK)     // 64

#define A_STAGE_FLOATS (BM * BK)           // 4096  (16 KB)
#define B_STAGE_FLOATS (BN * BK)           // 8192  (32 KB)
#define STAGE_FLOATS   (A_STAGE_FLOATS + B_STAGE_FLOATS)   // 12288
#define STAGE_BYTES    (STAGE_FLOATS * 4)                  // 49152
#define SMEM_DYN_BYTES (STAGES * STAGE_BYTES)              // 147456

// ---------------- device scratch ----------------
__device__ float g_W[(size_t)E_NUM * DOUT * DIN];     // tf32-rounded weights
__device__ float g_X[(size_t)E_NUM * T_MAX * DIN];    // gathered+rounded activations
__device__ float g_Y[(size_t)E_NUM * T_MAX * DOUT];   // per-slot expert outputs
__device__ int   g_cnt[E_NUM];
__device__ int   g_tok[E_NUM * T_MAX];
__device__ int   g_tslot[T_MAX * 2];
__device__ float g_tw[T_MAX * 2];

// ---------------- helpers ----------------
__device__ __forceinline__ uint32_t smem_u32(const void* p) {
    uint32_t a;
    asm("{ .reg .u64 t; cvta.to.shared.u64 t, %1; cvt.u32.u64 %0, t; }"
        : "=r"(a) : "l"(p));
    return a;
}
__device__ __forceinline__ unsigned f2tf32(float f) {
    unsigned u;
    asm("cvt.rna.tf32.f32 %0, %1;" : "=r"(u) : "f"(f));
    return u;
}
#define CP_ASYNC16(sa, ga) \
    asm volatile("cp.async.cg.shared.global [%0], [%1], 16;" :: "r"(sa), "l"(ga) : "memory")
#define CP_COMMIT() asm volatile("cp.async.commit_group;" ::: "memory")
template <int N>
__device__ __forceinline__ void cp_wait_group() {
    asm volatile("cp.async.wait_group %0;" :: "n"(N) : "memory");
}

// ---------------- kernel: zero counters ----------------
__global__ void zero_cnt_kernel() {
    if (threadIdx.x < E_NUM) g_cnt[threadIdx.x] = 0;
}

// ---------------- kernel: router ----------------
__global__ void router_kernel(const float* __restrict__ logits, int T) {
    int t = blockIdx.x * blockDim.x + threadIdx.x;
    if (t >= T) return;
    float l[E_NUM];
#pragma unroll
    for (int e = 0; e < E_NUM; e++) l[e] = logits[t * E_NUM + e];
    int i1 = 0; float v1 = l[0];
#pragma unroll
    for (int e = 1; e < E_NUM; e++)
        if (l[e] > v1) { v1 = l[e]; i1 = e; }
    int i2 = -1; float v2 = -3.4e38f;
#pragma unroll
    for (int e = 0; e < E_NUM; e++)
        if (e != i1 && l[e] > v2) { v2 = l[e]; i2 = e; }
    float w1 = 1.0f / (1.0f + expf(v2 - v1));
    float w2 = 1.0f - w1;
    int p1 = atomicAdd(&g_cnt[i1], 1);
    g_tok[i1 * T_MAX + p1] = t;
    int p2 = atomicAdd(&g_cnt[i2], 1);
    g_tok[i2 * T_MAX + p2] = t;
    g_tslot[2 * t]     = i1 * T_MAX + p1;  g_tw[2 * t]     = w1;
    g_tslot[2 * t + 1] = i2 * T_MAX + p2;  g_tw[2 * t + 1] = w2;
}

// ---------------- kernel: convert W -> tf32-rounded ----------------
__global__ void convert_w_kernel(const float4* __restrict__ W) {
    const int n4 = E_NUM * DOUT * (DIN / 4);
    float4* dst = (float4*)g_W;
    for (int i = blockIdx.x * blockDim.x + threadIdx.x; i < n4;
         i += gridDim.x * blockDim.x) {
        float4 v = W[i];
        v.x = __uint_as_float(f2tf32(v.x));
        v.y = __uint_as_float(f2tf32(v.y));
        v.z = __uint_as_float(f2tf32(v.z));
        v.w = __uint_as_float(f2tf32(v.w));
        dst[i] = v;
    }
}

// ---------------- kernel: gather + convert X rows per expert ----------------
__global__ void gather_x_kernel(const float* __restrict__ X) {
    int e = blockIdx.y;
    int i = blockIdx.x;
    if (i >= g_cnt[e]) return;
    int tok = g_tok[e * T_MAX + i];
    const float4* src = (const float4*)(X + (size_t)tok * DIN);
    float4* dst = (float4*)(g_X + ((size_t)e * T_MAX + i) * DIN);
    for (int j = threadIdx.x; j < DIN / 4; j += blockDim.x) {
        float4 v = src[j];
        v.x = __uint_as_float(f2tf32(v.x));
        v.y = __uint_as_float(f2tf32(v.y));
        v.z = __uint_as_float(f2tf32(v.z));
        v.w = __uint_as_float(f2tf32(v.w));
        dst[j] = v;
    }
}

// ---------------- kernel: grouped TF32 GEMM (mma.sync, cp.async pipeline) ----
// Y[e*T_MAX + m, n] = sum_k g_X[e*T_MAX + m, k] * g_W[e, n, k]
//
// SMEM per stage: A[4 slices][128 rows][8 k] then B[4][256][8].
// Within a row's 8 k-floats, halves are swapped when (row>>2)&1 so that both
// the cp.async 16B stores and the per-fragment LDS.32 (k=c, k=c+4) are
// bank-conflict-free. Stored position of k is k ^ (4*((row>>2)&1)).
__global__ void __launch_bounds__(256, 1)
moe_gemm_kernel() {
    int e   = blockIdx.z;
    int cnt = g_cnt[e];
    int m0  = blockIdx.y * BM;
    if (m0 >= cnt) return;
    int n0  = blockIdx.x * BN;

    extern __shared__ float smem[];
    uint32_t smem_addr = smem_u32(smem);

    int tid  = threadIdx.x;
    int warp = tid >> 5;
    int lane = tid & 31;
    int wm   = warp >> 2;          // 0..1 (M)
    int wn   = warp & 3;           // 0..3 (N)
    int g    = lane >> 2;          // 0..7
    int c    = lane & 3;           // 0..3

    // ---- cp.async source pointers + swizzled smem dst offsets (bytes) ----
    int rowL  = tid >> 1;                       // 0..127
    int khalf = (tid & 1) * 16;                 // k offset of this thread's 64B
    const char* gA  = (const char*)(g_X + ((size_t)e * T_MAX + m0 + rowL) * DIN + khalf);
    const char* gB0 = (const char*)(g_W + ((size_t)e * DOUT + n0 + rowL) * DIN + khalf);
    const char* gB1 = gB0 + (size_t)128 * DIN * 4;

    uint32_t dA[4], dB[4];
    int swA = ((rowL >> 2) & 1) * 4;
#pragma unroll
    for (int i = 0; i < 4; i++) {
        int k = khalf + i * 4;                  // k of this 16B chunk
        dA[i] = (((k >> 3) * BM + rowL) * 8 + ((k & 7) ^ swA)) * 4;
        dB[i] = (A_STAGE_FLOATS + ((k >> 3) * BN + rowL) * 8 + ((k & 7) ^ swA)) * 4;
    }
    const uint32_t dB1off = 128 * 8 * 4;        // +128 rows within a B slice

#define LOAD_STAGE(st, it)                                                    \
    do {                                                                      \
        uint32_t _sb = smem_addr + (st) * STAGE_BYTES;                        \
        const char* _ga  = gA  + (size_t)(it) * 128;                          \
        const char* _gb0 = gB0 + (size_t)(it) * 128;                          \
        const char* _gb1 = gB1 + (size_t)(it) * 128;                          \
        _Pragma("unroll")                                                     \
        for (int _i = 0; _i < 4; _i++) {                                      \
            CP_ASYNC16(_sb + dA[_i], _ga + _i * 16);                          \
            CP_ASYNC16(_sb + dB[_i], _gb0 + _i * 16);                         \
            CP_ASYNC16(_sb + dB[_i] + dB1off, _gb1 + _i * 16);                \
        }                                                                     \
    } while (0)

    float acc[4][8][4];
#pragma unroll
    for (int i = 0; i < 4; i++)
#pragma unroll
        for (int j = 0; j < 8; j++)
#pragma unroll
            for (int k = 0; k < 4; k++) acc[i][j][k] = 0.0f;

    // fragment row/col bases (compile-time friendly)
    int arow0 = wm * 64 + g;                    // + mt*16 (+8)
    int brow0 = wn * 64 + g;                    // + nt*8

#define COMPUTE_STAGE(st)                                                     \
    do {                                                                      \
        const float* _sa = smem + (st) * STAGE_FLOATS;                        \
        const float* _sb = _sa + A_STAGE_FLOATS;                              \
        _Pragma("unroll")                                                     \
        for (int s = 0; s < 4; s++) {                                         \
            unsigned af[4][4];                                                \
            _Pragma("unroll")                                                 \
            for (int mt = 0; mt < 4; mt++) {                                  \
                int r0 = arow0 + mt * 16;                                     \
                int sw = ((r0 >> 2) & 1) * 4;                                 \
                int i0 = (s * BM + r0) * 8 + (c ^ sw);                        \
                af[mt][0] = __float_as_uint(_sa[i0]);                         \
                af[mt][1] = __float_as_uint(_sa[i0 + 64]);  /* row+8 */       \
                af[mt][2] = __float_as_uint(_sa[i0 ^ 4]);                     \
                af[mt][3] = __float_as_uint(_sa[(i0 + 64) ^ 4]);              \
            }                                                                 \
            _Pragma("unroll")                                                 \
            for (int nt = 0; nt < 8; nt++) {                                  \
                int n  = brow0 + nt * 8;                                      \
                int sw = ((n >> 2) & 1) * 4;                                  \
                int i0 = (s * BN + n) * 8 + (c ^ sw);                         \
                unsigned b0 = __float_as_uint(_sb[i0]);                       \
                unsigned b1 = __float_as_uint(_sb[i0 ^ 4]);                   \
                _Pragma("unroll")                                             \
                for (int mt = 0; mt < 4; mt++) {                              \
                    asm volatile(                                             \
                        "mma.sync.aligned.m16n8k8.row.col.f32.tf32.tf32.f32 " \
                        "{%0,%1,%2,%3}, {%4,%5,%6,%7}, {%8,%9}, "             \
                        "{%0,%1,%2,%3};\n"                                    \
                        : "+f"(acc[mt][nt][0]), "+f"(acc[mt][nt][1]),         \
                          "+f"(acc[mt][nt][2]), "+f"(acc[mt][nt][3])          \
                        : "r"(af[mt][0]), "r"(af[mt][1]),                     \
                          "r"(af[mt][2]), "r"(af[mt][3]),                     \
                          "r"(b0), "r"(b1));                                  \
                }                                                             \
            }                                                                 \
        }                                                                     \
    } while (0)

    // ---- pipeline prologue: fill stages 0,1 ----
    LOAD_STAGE(0, 0); CP_COMMIT();
    LOAD_STAGE(1, 1); CP_COMMIT();

    int st = 0;
    for (int it = 0; it < KITERS; ++it) {
        cp_wait_group<1>();
        __syncthreads();
        if (it + 2 < KITERS) {
            int st2 = st + 2; if (st2 >= STAGES) st2 -= STAGES;
            LOAD_STAGE(st2, it + 2);
        }
        CP_COMMIT();
        COMPUTE_STAGE(st);
        if (++st == STAGES) st = 0;
    }

    // ---- epilogue: plain STG.64 into g_Y slot rows (no atomics) ----
    size_t ybase = ((size_t)e * T_MAX + m0) * DOUT + n0;
#pragma unroll
    for (int mt = 0; mt < 4; mt++) {
        int r0 = arow0 + mt * 16;
#pragma unroll
        for (int nt = 0; nt < 8; nt++) {
            int col = brow0 - g + nt * 8 + 2 * c;   // wn*64 + nt*8 + 2c
            float2 lo = make_float2(acc[mt][nt][0], acc[mt][nt][1]);
            float2 hi = make_float2(acc[mt][nt][2], acc[mt][nt][3]);
            *(float2*)&g_Y[ybase + (size_t)r0 * DOUT + col]       = lo;
            *(float2*)&g_Y[ybase + (size_t)(r0 + 8) * DOUT + col] = hi;
        }
    }
#undef LOAD_STAGE
#undef COMPUTE_STAGE
}

// ---------------- kernel: combine two expert slots + bias -> out -------------
__global__ void combine_kernel(const float* __restrict__ Bias,
                               float* __restrict__ Out) {
    int t = blockIdx.x;
    int s1 = g_tslot[2 * t], s2 = g_tslot[2 * t + 1];
    float w1 = g_tw[2 * t],  w2 = g_tw[2 * t + 1];
    int e1 = s1 >> 12, e2 = s2 >> 12;          // T_MAX = 4096
    const float4* y1 = (const float4*)(g_Y + (size_t)s1 * DOUT);
    const float4* y2 = (const float4*)(g_Y + (size_t)s2 * DOUT);
    const float4* b1 = (const float4*)(Bias + (size_t)e1 * DOUT);
    const float4* b2 = (const float4*)(Bias + (size_t)e2 * DOUT);
    float4* o = (float4*)(Out + (size_t)t * DOUT);
    for (int j = threadIdx.x; j < DOUT / 4; j += blockDim.x) {
        float4 a = y1[j], b = b1[j], cc = y2[j], d = b2[j], r;
        r.x = w1 * (a.x + b.x) + w2 * (cc.x + d.x);
        r.y = w1 * (a.y + b.y) + w2 * (cc.y + d.y);
        r.z = w1 * (a.z + b.z) + w2 * (cc.z + d.z);
        r.w = w1 * (a.w + b.w) + w2 * (cc.w + d.w);
        o[j] = r;
    }
}

// ---------------- launcher ----------------
extern "C" void kernel_launch(void* const* d_in, const int* in_sizes, int n_in,
                              void* d_out, int out_size) {
    const float* X      = (const float*)d_in[0];
    const float* logits = (const float*)d_in[1];
    const float* W      = (const float*)d_in[2];
    const float* B      = (const float*)d_in[3];
    float* Out          = (float*)d_out;
    int T = in_sizes[1] / E_NUM;               // 4096

    static int smem_set = 0;
    if (!smem_set) {
        cudaFuncSetAttribute(moe_gemm_kernel,
                             cudaFuncAttributeMaxDynamicSharedMemorySize,
                             SMEM_DYN_BYTES);
        smem_set = 1;
    }

    zero_cnt_kernel<<<1, 32>>>();
    router_kernel<<<(T + 255) / 256, 256>>>(logits, T);
    convert_w_kernel<<<4096, 256>>>((const float4*)W);
    gather_x_kernel<<<dim3(T_MAX, E_NUM), 128>>>(X);

    dim3 grid(DOUT / BN, T_MAX / BM, E_NUM);
    moe_gemm_kernel<<<grid, 256, SMEM_DYN_BYTES>>>();

    combine_kernel<<<T, 256>>>(B, Out);
}

// round 4
// speedup vs baseline: 2.4331x; 1.9712x over previous
#include <cuda_runtime.h>
#include <cstdint>
#include <cstddef>

// ---------------- problem constants ----------------
#define E_NUM 8
#define T_MAX 4096
#define DIN   2048
#define DOUT  2048

// GEMM tiling: CTA 128x256, 8 warps (2 M x 4 N), warp tile 64x64, BK=32
#define BM 128
#define BN 256
#define BK 32
#define STAGES 4
#define KITERS (DIN / BK)     // 64

#define A_STAGE_FLOATS (BM * BK)           // 4096  (16 KB)
#define B_STAGE_FLOATS (BN * BK)           // 8192  (32 KB)
#define STAGE_FLOATS   (A_STAGE_FLOATS + B_STAGE_FLOATS)   // 12288
#define A_STAGE_BYTES  (A_STAGE_FLOATS * 4)                // 16384
#define B_STAGE_BYTES  (B_STAGE_FLOATS * 4)                // 32768
#define STAGE_BYTES    (STAGE_FLOATS * 4)                  // 49152
#define SMEM_DYN_BYTES (STAGES * STAGE_BYTES)              // 196608

// ---------------- device scratch ----------------
// Packed, tf32-rounded, pre-swizzled operands (smem-image layout):
//   g_Wp: [e][ntile=8][kstage=64][ (slice*256+row)*8 + (kin^sw) ]   (8192 f/blk)
//   g_Xp: [e][mtile=32][kstage=64][ (slice*128+row)*8 + (kin^sw) ]  (4096 f/blk)
// where slice=(k>>3)&3, kin=k&7, sw = 4*((row>>2)&1)
__device__ float g_Wp[(size_t)E_NUM * DOUT * DIN];
__device__ float g_Xp[(size_t)E_NUM * T_MAX * DIN];
__device__ float g_Y[(size_t)E_NUM * T_MAX * DOUT];
__device__ int   g_cnt[E_NUM];
__device__ int   g_tok[E_NUM * T_MAX];
__device__ int   g_tslot[T_MAX * 2];
__device__ float g_tw[T_MAX * 2];

// ---------------- helpers ----------------
__device__ __forceinline__ uint32_t smem_u32(const void* p) {
    uint32_t a;
    asm("{ .reg .u64 t; cvta.to.shared.u64 t, %1; cvt.u32.u64 %0, t; }"
        : "=r"(a) : "l"(p));
    return a;
}
__device__ __forceinline__ unsigned f2tf32(float f) {
    unsigned u;
    asm("cvt.rna.tf32.f32 %0, %1;" : "=r"(u) : "f"(f));
    return u;
}
__device__ __forceinline__ float4 round4(float4 v) {
    v.x = __uint_as_float(f2tf32(v.x));
    v.y = __uint_as_float(f2tf32(v.y));
    v.z = __uint_as_float(f2tf32(v.z));
    v.w = __uint_as_float(f2tf32(v.w));
    return v;
}

#define MBARRIER_INIT(addr, cnt) \
    asm volatile("mbarrier.init.shared.b64 [%0], %1;" :: "r"(addr), "r"(cnt) : "memory")
#define MBARRIER_EXPECT_TX(addr, tx) \
    asm volatile("mbarrier.arrive.expect_tx.shared.b64 _, [%0], %1;" \
                 :: "r"(addr), "r"(tx) : "memory")
#define MBARRIER_WAIT_PARITY(addr, ph) do {                                   \
    uint32_t _m = (addr); uint32_t _p = (ph); uint32_t _d;                    \
    asm volatile("{\n\t.reg .pred p;\n\t"                                     \
        "mbarrier.try_wait.parity.acquire.cta.shared::cta.b64 p, [%1], %2;\n\t"\
        "selp.b32 %0, 1, 0, p;\n\t}"                                          \
        : "=r"(_d) : "r"(_m), "r"(_p) : "memory");                            \
    if (!_d) {                                                                \
        asm volatile("{\n\t.reg .pred P1;\n\t"                                \
            "WL_%=:\n\t"                                                      \
            "mbarrier.try_wait.parity.acquire.cta.shared::cta.b64 P1, [%0], %1, 0x989680;\n\t" \
            "@P1 bra.uni WD_%=;\n\t"                                          \
            "bra.uni WL_%=;\n\t"                                              \
            "WD_%=:\n\t}" :: "r"(_m), "r"(_p) : "memory");                    \
    }                                                                         \
} while (0)

__device__ __forceinline__ void bulk_ld(uint32_t sdst, const void* gsrc,
                                        uint32_t bytes, uint32_t mbar) {
    asm volatile(
        "cp.async.bulk.shared::cluster.global.mbarrier::complete_tx::bytes "
        "[%0], [%1], %2, [%3];"
        :: "r"(sdst), "l"(gsrc), "r"(bytes), "r"(mbar) : "memory");
}

// ---------------- kernel: zero counters ----------------
__global__ void zero_cnt_kernel() {
    if (threadIdx.x < E_NUM) g_cnt[threadIdx.x] = 0;
}

// ---------------- kernel: router ----------------
__global__ void router_kernel(const float* __restrict__ logits, int T) {
    int t = blockIdx.x * blockDim.x + threadIdx.x;
    if (t >= T) return;
    float l[E_NUM];
#pragma unroll
    for (int e = 0; e < E_NUM; e++) l[e] = logits[t * E_NUM + e];
    int i1 = 0; float v1 = l[0];
#pragma unroll
    for (int e = 1; e < E_NUM; e++)
        if (l[e] > v1) { v1 = l[e]; i1 = e; }
    int i2 = -1; float v2 = -3.4e38f;
#pragma unroll
    for (int e = 0; e < E_NUM; e++)
        if (e != i1 && l[e] > v2) { v2 = l[e]; i2 = e; }
    float w1 = 1.0f / (1.0f + expf(v2 - v1));
    float w2 = 1.0f - w1;
    int p1 = atomicAdd(&g_cnt[i1], 1);
    g_tok[i1 * T_MAX + p1] = t;
    int p2 = atomicAdd(&g_cnt[i2], 1);
    g_tok[i2 * T_MAX + p2] = t;
    g_tslot[2 * t]     = i1 * T_MAX + p1;  g_tw[2 * t]     = w1;
    g_tslot[2 * t + 1] = i2 * T_MAX + p2;  g_tw[2 * t + 1] = w2;
}

// packed in-block float4-chunk offset for (row, chunk j), rowsz = BM or BN
__device__ __forceinline__ uint32_t pack_off(int row, int j, int rowsz) {
    int slice = (j >> 1) & 3;                 // (k>>3)&3, k = j*4
    int kin   = (j & 1) * 4;                  // k&7 (4-aligned)
    int sw    = ((row >> 2) & 1) * 4;
    return (uint32_t)(((j >> 3) * (rowsz * BK)) +      // kstage * blockfloats
                      (slice * rowsz + row) * 8 + (kin ^ sw));
}

// ---------------- kernel: convert+pack W ----------------
__global__ void convert_w_kernel(const float4* __restrict__ W) {
    const int n4 = E_NUM * DOUT * (DIN / 4);
    for (int i = blockIdx.x * blockDim.x + threadIdx.x; i < n4;
         i += gridDim.x * blockDim.x) {
        int j   = i & 511;                    // chunk in row (k = j*4)
        int n   = (i >> 9) & (DOUT - 1);
        int e   = i >> 20;                    // / (2048*512)
        float4 v = round4(W[i]);
        size_t blk = ((size_t)e * 8 + (n >> 8)) * (64 * B_STAGE_FLOATS);
        *(float4*)&g_Wp[blk + pack_off(n & 255, j, BN)] = v;
    }
}

// ---------------- kernel: gather + convert + pack X ----------------
__global__ void gather_x_kernel(const float* __restrict__ X) {
    int e = blockIdx.y;
    int i = blockIdx.x;                       // slot in expert list
    if (i >= g_cnt[e]) return;
    int tok = g_tok[e * T_MAX + i];
    const float4* src = (const float4*)(X + (size_t)tok * DIN);
    size_t blk = ((size_t)e * 32 + (i >> 7)) * (64 * A_STAGE_FLOATS);
    int row = i & 127;
    for (int j = threadIdx.x; j < DIN / 4; j += blockDim.x)
        *(float4*)&g_Xp[blk + pack_off(row, j, BM)] = round4(src[j]);
}

// ---------------- kernel: grouped TF32 GEMM (bulk-TMA pipeline) ----------
// Y[e*T_MAX + m, n] = sum_k X[m,k] * W[e,n,k]
__global__ void __launch_bounds__(256, 1)
moe_gemm_kernel() {
    int e   = blockIdx.z;
    int cnt = g_cnt[e];
    int m0  = blockIdx.y * BM;
    if (m0 >= cnt) return;
    int n0  = blockIdx.x * BN;

    extern __shared__ __align__(1024) float smem[];
    __shared__ __align__(8) uint64_t mbar_full[STAGES];
    uint32_t smem_addr = smem_u32(smem);
    uint32_t mb = smem_u32(mbar_full);

    int tid  = threadIdx.x;
    int warp = tid >> 5;
    int lane = tid & 31;
    int wm   = warp >> 2;
    int wn   = warp & 3;
    int g    = lane >> 2;
    int c    = lane & 3;

    if (tid == 0) {
#pragma unroll
        for (int s = 0; s < STAGES; s++) MBARRIER_INIT(mb + 8 * s, 1);
    }
    __syncthreads();

    const char* gA = (const char*)(g_Xp +
        ((size_t)e * 32 + blockIdx.y) * (64 * A_STAGE_FLOATS));
    const char* gB = (const char*)(g_Wp +
        ((size_t)e * 8 + blockIdx.x) * (64 * B_STAGE_FLOATS));

#define ISSUE(it)                                                             \
    do {                                                                      \
        int _s = (it) & (STAGES - 1);                                         \
        uint32_t _m = mb + 8 * _s;                                            \
        MBARRIER_EXPECT_TX(_m, STAGE_BYTES);                                  \
        bulk_ld(smem_addr + _s * STAGE_BYTES,                                 \
                gA + (size_t)(it) * A_STAGE_BYTES, A_STAGE_BYTES, _m);        \
        bulk_ld(smem_addr + _s * STAGE_BYTES + A_STAGE_BYTES,                 \
                gB + (size_t)(it) * B_STAGE_BYTES, B_STAGE_BYTES, _m);        \
    } while (0)

    if (tid == 0) { ISSUE(0); ISSUE(1); ISSUE(2); }

    float acc[4][8][4];
#pragma unroll
    for (int i = 0; i < 4; i++)
#pragma unroll
        for (int j = 0; j < 8; j++)
#pragma unroll
            for (int k = 0; k < 4; k++) acc[i][j][k] = 0.0f;

    int arow0 = wm * 64 + g;
    int brow0 = wn * 64 + g;

#define COMPUTE_STAGE(st)                                                     \
    do {                                                                      \
        const float* _sa = smem + (st) * STAGE_FLOATS;                        \
        const float* _sb = _sa + A_STAGE_FLOATS;                              \
        _Pragma("unroll")                                                     \
        for (int s = 0; s < 4; s++) {                                         \
            unsigned af[4][4];                                                \
            _Pragma("unroll")                                                 \
            for (int mt = 0; mt < 4; mt++) {                                  \
                int r0 = arow0 + mt * 16;                                     \
                int sw = ((r0 >> 2) & 1) * 4;                                 \
                int i0 = (s * BM + r0) * 8 + (c ^ sw);                        \
                af[mt][0] = __float_as_uint(_sa[i0]);                         \
                af[mt][1] = __float_as_uint(_sa[i0 + 64]);  /* row+8 */       \
                af[mt][2] = __float_as_uint(_sa[i0 ^ 4]);                     \
                af[mt][3] = __float_as_uint(_sa[(i0 + 64) ^ 4]);              \
            }                                                                 \
            _Pragma("unroll")                                                 \
            for (int nt = 0; nt < 8; nt++) {                                  \
                int n  = brow0 + nt * 8;                                      \
                int sw = ((n >> 2) & 1) * 4;                                  \
                int i0 = (s * BN + n) * 8 + (c ^ sw);                         \
                unsigned b0 = __float_as_uint(_sb[i0]);                       \
                unsigned b1 = __float_as_uint(_sb[i0 ^ 4]);                   \
                _Pragma("unroll")                                             \
                for (int mt = 0; mt < 4; mt++) {                              \
                    asm volatile(                                             \
                        "mma.sync.aligned.m16n8k8.row.col.f32.tf32.tf32.f32 " \
                        "{%0,%1,%2,%3}, {%4,%5,%6,%7}, {%8,%9}, "             \
                        "{%0,%1,%2,%3};\n"                                    \
                        : "+f"(acc[mt][nt][0]), "+f"(acc[mt][nt][1]),         \
                          "+f"(acc[mt][nt][2]), "+f"(acc[mt][nt][3])         \
                        : "r"(af[mt][0]), "r"(af[mt][1]),                     \
                          "r"(af[mt][2]), "r"(af[mt][3]),                     \
                          "r"(b0), "r"(b1));                                  \
                }                                                             \
            }                                                                 \
        }                                                                     \
    } while (0)

    for (int it = 0; it < KITERS; ++it) {
        int s = it & (STAGES - 1);
        MBARRIER_WAIT_PARITY(mb + 8 * s, (it >> 2) & 1);
        // slot (it+3)&3 == slot (it-1)&3, freed by last iteration's barrier
        if (tid == 0 && it + 3 < KITERS) ISSUE(it + 3);
        COMPUTE_STAGE(s);
        __syncthreads();
    }

    // ---- epilogue: plain STG.64 into g_Y slot rows (no atomics) ----
    size_t ybase = ((size_t)e * T_MAX + m0) * DOUT + n0;
#pragma unroll
    for (int mt = 0; mt < 4; mt++) {
        int r0 = arow0 + mt * 16;
#pragma unroll
        for (int nt = 0; nt < 8; nt++) {
            int col = wn * 64 + nt * 8 + 2 * c;
            float2 lo = make_float2(acc[mt][nt][0], acc[mt][nt][1]);
            float2 hi = make_float2(acc[mt][nt][2], acc[mt][nt][3]);
            *(float2*)&g_Y[ybase + (size_t)r0 * DOUT + col]       = lo;
            *(float2*)&g_Y[ybase + (size_t)(r0 + 8) * DOUT + col] = hi;
        }
    }
#undef ISSUE
#undef COMPUTE_STAGE
}

// ---------------- kernel: combine two expert slots + bias -> out -------------
__global__ void combine_kernel(const float* __restrict__ Bias,
                               float* __restrict__ Out) {
    int t = blockIdx.x;
    int s1 = g_tslot[2 * t], s2 = g_tslot[2 * t + 1];
    float w1 = g_tw[2 * t],  w2 = g_tw[2 * t + 1];
    int e1 = s1 >> 12, e2 = s2 >> 12;          // T_MAX = 4096
    const float4* y1 = (const float4*)(g_Y + (size_t)s1 * DOUT);
    const float4* y2 = (const float4*)(g_Y + (size_t)s2 * DOUT);
    const float4* b1 = (const float4*)(Bias + (size_t)e1 * DOUT);
    const float4* b2 = (const float4*)(Bias + (size_t)e2 * DOUT);
    float4* o = (float4*)(Out + (size_t)t * DOUT);
    for (int j = threadIdx.x; j < DOUT / 4; j += blockDim.x) {
        float4 a = y1[j], b = b1[j], cc = y2[j], d = b2[j], r;
        r.x = w1 * (a.x + b.x) + w2 * (cc.x + d.x);
        r.y = w1 * (a.y + b.y) + w2 * (cc.y + d.y);
        r.z = w1 * (a.z + b.z) + w2 * (cc.z + d.z);
        r.w = w1 * (a.w + b.w) + w2 * (cc.w + d.w);
        o[j] = r;
    }
}

// ---------------- launcher ----------------
extern "C" void kernel_launch(void* const* d_in, const int* in_sizes, int n_in,
                              void* d_out, int out_size) {
    const float* X      = (const float*)d_in[0];
    const float* logits = (const float*)d_in[1];
    const float* W      = (const float*)d_in[2];
    const float* B      = (const float*)d_in[3];
    float* Out          = (float*)d_out;
    int T = in_sizes[1] / E_NUM;               // 4096

    static int smem_set = 0;
    if (!smem_set) {
        cudaFuncSetAttribute(moe_gemm_kernel,
                             cudaFuncAttributeMaxDynamicSharedMemorySize,
                             SMEM_DYN_BYTES);
        smem_set = 1;
    }

    zero_cnt_kernel<<<1, 32>>>();
    router_kernel<<<(T + 255) / 256, 256>>>(logits, T);
    convert_w_kernel<<<4096, 256>>>((const float4*)W);
    gather_x_kernel<<<dim3(T_MAX, E_NUM), 128>>>(X);

    dim3 grid(DOUT / BN, T_MAX / BM, E_NUM);
    moe_gemm_kernel<<<grid, 256, SMEM_DYN_BYTES>>>();

    combine_kernel<<<T, 256>>>(B, Out);
}